// round 1
// baseline (speedup 1.0000x reference)
#include <cuda_runtime.h>
#include <cuda_bf16.h>

#define NN 100000
#define NE 1600000
#define NG 64
#define HID 64
#define INDIM 128

// Scratch (alloc-free rule: __device__ globals). float4 for 16B alignment.
__device__ float4 g_buf1[NN * 16];   // GEMM output (scaled by norm_out), SpMM source
__device__ float4 g_buf2[NN * 16];   // layer activations / gated output
__device__ float4 g_m[NN * 16];      // SpMM accumulator
__device__ float  g_norm_out[NN];
__device__ float  g_norm_in[NN];
__device__ int    g_deg_out[NN];
__device__ int    g_deg_in[NN];
__device__ int    g_cnt[NG];
__device__ int    g_off[NG + 1];

// ---------------------------------------------------------------------------
__global__ void zero_kernel() {
    int i = blockIdx.x * blockDim.x + threadIdx.x;
    if (i < NN) { g_deg_out[i] = 0; g_deg_in[i] = 0; }
    if (i < NG) g_cnt[i] = 0;
}

__global__ void degree_kernel(const int* __restrict__ ei) {
    int e = blockIdx.x * blockDim.x + threadIdx.x;
    if (e < NE) {
        atomicAdd(&g_deg_out[ei[e]], 1);
        atomicAdd(&g_deg_in[ei[NE + e]], 1);
    }
}

__global__ void norm_hist_kernel(const int* __restrict__ gid) {
    int n = blockIdx.x * blockDim.x + threadIdx.x;
    if (n < NN) {
        g_norm_out[n] = rsqrtf((float)max(g_deg_out[n], 1));
        g_norm_in[n]  = rsqrtf((float)max(g_deg_in[n], 1));
        atomicAdd(&g_cnt[gid[n]], 1);  // sorted graph_id -> warp-uniform, REDUX-aggregated
    }
}

__global__ void prefix_kernel() {
    if (threadIdx.x == 0) {
        int r = 0;
        for (int g = 0; g < NG; g++) { g_off[g] = r; r += g_cnt[g]; }
        g_off[NG] = r;
    }
}

// GEMM: buf1[n][c] = (X[n] @ W)[c] * norm_out[n]; also zeroes g_m for the SpMM.
// 256 threads: 4 nodes x 64 cols per chunk, 4 chunks per block -> 16 nodes/block.
template <int IN, bool FROM_BUF2>
__global__ void gemm_scale_kernel(const float* __restrict__ Xext,
                                  const float* __restrict__ W) {
    __shared__ float Ws[IN * 64];
    __shared__ float Xs[4][IN];
    const float* X = FROM_BUF2 ? (const float*)g_buf2 : Xext;

    int tid = threadIdx.x;
    for (int i = tid; i < IN * 64; i += 256) Ws[i] = W[i];

    int col = tid & 63;
    int sub = tid >> 6;
    int base = blockIdx.x * 16;

    for (int chunk = 0; chunk < 4; ++chunk) {
        int n0 = base + chunk * 4;
        __syncthreads();                 // Ws ready (chunk 0) / prev compute done
        for (int i = tid; i < 4 * IN; i += 256) {
            int r = i / IN, j = i % IN;
            int n = n0 + r;
            Xs[r][j] = (n < NN) ? X[n * IN + j] : 0.f;
        }
        __syncthreads();
        int n = n0 + sub;
        if (n < NN) {
            float acc = 0.f;
#pragma unroll
            for (int j = 0; j < IN; ++j)
                acc += Xs[sub][j] * Ws[j * 64 + col];
            ((float*)g_buf1)[n * 64 + col] = acc * g_norm_out[n];
            ((float*)g_m)[n * 64 + col] = 0.f;
        }
    }
}

// SpMM: m[dst] += buf1[src]. 16 threads per edge, float4 gather + red.v4 atomic.
__global__ void spmm_kernel(const int* __restrict__ ei) {
    int idx = blockIdx.x * blockDim.x + threadIdx.x;
    int e = idx >> 4;
    if (e >= NE) return;
    int lane = idx & 15;
    int s = __ldg(&ei[e]);
    int d = __ldg(&ei[NE + e]);
    float4 v = g_buf1[s * 16 + lane];
    float* p = (float*)&g_m[d * 16 + lane];
    asm volatile("red.global.add.v4.f32 [%0], {%1,%2,%3,%4};"
                 :: "l"(p), "f"(v.x), "f"(v.y), "f"(v.z), "f"(v.w) : "memory");
}

// buf2[n][c] = relu(m[n][c] * norm_in[n] + b1[c])
__global__ void post1_kernel(const float* __restrict__ b1) {
    int i = blockIdx.x * blockDim.x + threadIdx.x;
    if (i < NN * 64) {
        int n = i >> 6, c = i & 63;
        float v = ((const float*)g_m)[i] * g_norm_in[n] + __ldg(&b1[c]);
        ((float*)g_buf2)[i] = fmaxf(v, 0.f);
    }
}

// Final layer-2 epilogue: h = relu(m*norm_in + b2); hw = sigmoid(h . attn_W + ab);
// write hw; buf2 = h * hw. 32 threads (one warp) per node, 2 cols per lane.
__global__ void final_kernel(const float* __restrict__ b2,
                             const float* __restrict__ aW,
                             const float* __restrict__ ab,
                             float* __restrict__ hw_out) {
    int tid = threadIdx.x;
    int n = blockIdx.x * 8 + (tid >> 5);
    int lane = tid & 31;
    if (n >= NN) return;
    float ni = g_norm_in[n];
    const float* mrow = (const float*)&g_m[n * 16];
    float h0 = fmaxf(mrow[lane]      * ni + __ldg(&b2[lane]),      0.f);
    float h1 = fmaxf(mrow[lane + 32] * ni + __ldg(&b2[lane + 32]), 0.f);
    float p = h0 * __ldg(&aW[lane]) + h1 * __ldg(&aW[lane + 32]);
#pragma unroll
    for (int o = 16; o; o >>= 1) p += __shfl_xor_sync(0xffffffffu, p, o);
    float z = p + __ldg(&ab[0]);
    float hw = 1.f / (1.f + expf(-z));
    if (lane == 0) hw_out[n] = hw;
    float* orow = (float*)&g_buf2[n * 16];
    orow[lane]      = h0 * hw;
    orow[lane + 32] = h1 * hw;
}

// Per-graph mean pooling over sorted segments + classifier. One block per graph.
__global__ void pool_cls_kernel(const float* __restrict__ clsW,
                                const float* __restrict__ clsb,
                                float* __restrict__ out) {
    __shared__ float part[4][64];
    __shared__ float meanv[64];
    int g = blockIdx.x;
    int tid = threadIdx.x;
    int c = tid & 63, s = tid >> 6;
    int start = g_off[g], end = g_off[g + 1];
    float acc = 0.f;
    for (int n = start + s; n < end; n += 4)
        acc += ((const float*)g_buf2)[n * 64 + c];
    part[s][c] = acc;
    __syncthreads();
    if (s == 0) {
        float tot = part[0][c] + part[1][c] + part[2][c] + part[3][c];
        float cnt = fmaxf((float)(end - start), 1.f);
        meanv[c] = tot / cnt;
    }
    __syncthreads();
    if (tid < 10) {
        float a2 = __ldg(&clsb[tid]);
#pragma unroll
        for (int k = 0; k < 64; k++)
            a2 += meanv[k] * __ldg(&clsW[k * 10 + tid]);
        out[g * 10 + tid] = a2;
    }
}

// ---------------------------------------------------------------------------
extern "C" void kernel_launch(void* const* d_in, const int* in_sizes, int n_in,
                              void* d_out, int out_size) {
    const float* x   = (const float*)d_in[0];
    const int*   ei  = (const int*)  d_in[1];
    const int*   gid = (const int*)  d_in[2];
    const float* W1  = (const float*)d_in[3];
    const float* b1  = (const float*)d_in[4];
    const float* W2  = (const float*)d_in[5];
    const float* b2  = (const float*)d_in[6];
    const float* aW  = (const float*)d_in[7];
    const float* ab  = (const float*)d_in[8];
    const float* cW  = (const float*)d_in[9];
    const float* cb  = (const float*)d_in[10];
    float* out = (float*)d_out;
    float* hw  = out + NG * 10;   // tuple layout: out[64,10] then hw[100000,1]

    zero_kernel<<<(NN + 255) / 256, 256>>>();
    degree_kernel<<<(NE + 255) / 256, 256>>>(ei);
    norm_hist_kernel<<<(NN + 255) / 256, 256>>>(gid);
    prefix_kernel<<<1, 32>>>();

    // Layer 1
    gemm_scale_kernel<INDIM, false><<<(NN + 15) / 16, 256>>>(x, W1);
    spmm_kernel<<<(NE * 16 + 255) / 256, 256>>>(ei);
    post1_kernel<<<(NN * 64 + 255) / 256, 256>>>(b1);

    // Layer 2
    gemm_scale_kernel<HID, true><<<(NN + 15) / 16, 256>>>(nullptr, W2);
    spmm_kernel<<<(NE * 16 + 255) / 256, 256>>>(ei);
    final_kernel<<<(NN + 7) / 8, 256>>>(b2, aW, ab, hw);

    // Readout
    pool_cls_kernel<<<NG, 256>>>(cW, cb, out);
}

// round 3
// speedup vs baseline: 1.5790x; 1.5790x over previous
#include <cuda_runtime.h>
#include <cuda_bf16.h>

#define NN 100000
#define NE 1600000
#define NG 64
#define HID 64
#define INDIM 128
#define SBS 512
#define NB ((NN + SBS - 1) / SBS)

// Scratch (__device__ globals per alloc-free rule)
__device__ float4 g_buf1[NN * 16];   // GEMM output scaled by norm_out (SpMM source)
__device__ float4 g_buf2[NN * 16];   // activations / gated output
__device__ float  g_norm_out[NN];
__device__ float  g_norm_in[NN];
__device__ int    g_deg_out[NN];
__device__ int    g_deg_in[NN];
__device__ int    g_fill[NN];
__device__ int    g_row_off[NN + 1];
__device__ int    g_csr_src[NE];
__device__ int    g_bsum[NB];
__device__ int    g_boff[NB];
__device__ int    g_cnt[NG];
__device__ int    g_off[NG + 1];

// ---------------------------------------------------------------------------
__global__ void zero_kernel() {
    int i = blockIdx.x * blockDim.x + threadIdx.x;
    if (i < NN) { g_deg_out[i] = 0; g_deg_in[i] = 0; g_fill[i] = 0; }
    if (i < NG) g_cnt[i] = 0;
}

__global__ void degree_kernel(const int* __restrict__ ei) {
    int e = blockIdx.x * blockDim.x + threadIdx.x;
    if (e < NE) {
        atomicAdd(&g_deg_out[ei[e]], 1);
        atomicAdd(&g_deg_in[ei[NE + e]], 1);
    }
}

// Per-block sums of deg_in for the scan; also graph-id histogram (sorted -> aggregated)
__global__ void scan1_kernel(const int* __restrict__ gid) {
    __shared__ int sh[SBS];
    int i = blockIdx.x * SBS + threadIdx.x;
    int v = (i < NN) ? g_deg_in[i] : 0;
    sh[threadIdx.x] = v;
    if (i < NN) atomicAdd(&g_cnt[gid[i]], 1);
    __syncthreads();
    for (int o = SBS / 2; o; o >>= 1) {
        if (threadIdx.x < o) sh[threadIdx.x] += sh[threadIdx.x + o];
        __syncthreads();
    }
    if (threadIdx.x == 0) g_bsum[blockIdx.x] = sh[0];
}

__global__ void scan2_kernel() {
    if (threadIdx.x == 0) {
        int r = 0;
        for (int b = 0; b < NB; b++) { g_boff[b] = r; r += g_bsum[b]; }
    }
}

__global__ void prefix_kernel() {
    if (threadIdx.x == 0) {
        int r = 0;
        for (int g = 0; g < NG; g++) { g_off[g] = r; r += g_cnt[g]; }
        g_off[NG] = r;
    }
}

// Intra-block exclusive scan -> row offsets; also compute norms.
__global__ void scan3_kernel() {
    __shared__ int sh[SBS];
    int i = blockIdx.x * SBS + threadIdx.x;
    int v = (i < NN) ? g_deg_in[i] : 0;
    sh[threadIdx.x] = v;
    __syncthreads();
    for (int o = 1; o < SBS; o <<= 1) {
        int t = (threadIdx.x >= o) ? sh[threadIdx.x - o] : 0;
        __syncthreads();
        sh[threadIdx.x] += t;
        __syncthreads();
    }
    if (i < NN) {
        g_row_off[i] = g_boff[blockIdx.x] + sh[threadIdx.x] - v;
        g_norm_in[i]  = rsqrtf((float)max(v, 1));
        g_norm_out[i] = rsqrtf((float)max(g_deg_out[i], 1));
    }
    if (i == 0) g_row_off[NN] = NE;
}

__global__ void scatter_kernel(const int* __restrict__ ei) {
    int e = blockIdx.x * blockDim.x + threadIdx.x;
    if (e < NE) {
        int d = ei[NE + e];
        int pos = g_row_off[d] + atomicAdd(&g_fill[d], 1);
        g_csr_src[pos] = ei[e];
    }
}

// ---------------------------------------------------------------------------
// GEMM: buf1[n][c] = (X[n] @ W)[c] * norm_out[n].
// 256 threads = 64 cols x 4 subs; each thread computes 4 nodes (register-blocked),
// 16 tiles of 16 nodes per block -> 256 nodes/block.
template <int IN, bool FROM_BUF2>
__global__ void gemm_kernel(const float* __restrict__ Xext,
                            const float* __restrict__ W) {
    __shared__ float Ws[IN * 64];
    __shared__ float Xs[16][IN];
    const float* X = FROM_BUF2 ? (const float*)g_buf2 : Xext;
    int tid = threadIdx.x;
    for (int i = tid; i < IN * 64; i += 256) Ws[i] = W[i];
    int col = tid & 63;
    int sub = tid >> 6;

    for (int t = 0; t < 16; ++t) {
        int n0 = blockIdx.x * 256 + t * 16;
        if (n0 >= NN) break;
        __syncthreads();
        for (int i = tid; i < 16 * (IN / 4); i += 256) {
            int r = i / (IN / 4), jc = i % (IN / 4);
            int n = n0 + r;
            float4 v = (n < NN) ? ((const float4*)(X + (long)n * IN))[jc]
                                : make_float4(0.f, 0.f, 0.f, 0.f);
            ((float4*)Xs[r])[jc] = v;
        }
        __syncthreads();
        float acc0 = 0.f, acc1 = 0.f, acc2 = 0.f, acc3 = 0.f;
        int r0 = sub * 4;
#pragma unroll 4
        for (int j = 0; j < IN; ++j) {
            float w = Ws[j * 64 + col];
            acc0 += Xs[r0 + 0][j] * w;
            acc1 += Xs[r0 + 1][j] * w;
            acc2 += Xs[r0 + 2][j] * w;
            acc3 += Xs[r0 + 3][j] * w;
        }
        int n = n0 + r0;
        float* B1 = (float*)g_buf1;
        if (n + 3 < NN) {
            B1[(n + 0) * 64 + col] = acc0 * g_norm_out[n + 0];
            B1[(n + 1) * 64 + col] = acc1 * g_norm_out[n + 1];
            B1[(n + 2) * 64 + col] = acc2 * g_norm_out[n + 2];
            B1[(n + 3) * 64 + col] = acc3 * g_norm_out[n + 3];
        } else {
            float a[4] = {acc0, acc1, acc2, acc3};
            for (int r = 0; r < 4; ++r)
                if (n + r < NN) B1[(n + r) * 64 + col] = a[r] * g_norm_out[n + r];
        }
    }
}

// ---------------------------------------------------------------------------
// CSR SpMM + fused epilogue. 16 lanes per dst node (one float4 col-chunk/lane),
// accumulate neighbor rows in registers, no atomics, no accumulator buffer.
template <bool FINAL>
__global__ void spmm_kernel(const float* __restrict__ bias,
                            const float* __restrict__ aW,
                            const float* __restrict__ ab,
                            float* __restrict__ hw_out) {
    int tid = threadIdx.x;
    int n = blockIdx.x * 16 + (tid >> 4);
    if (n >= NN) return;
    int lane = tid & 15;
    int beg = g_row_off[n], end = g_row_off[n + 1];
    float4 acc = make_float4(0.f, 0.f, 0.f, 0.f);
    int k = beg;
    for (; k + 1 < end; k += 2) {   // 2-way to break the load latency chain
        int s0 = __ldg(&g_csr_src[k]);
        int s1 = __ldg(&g_csr_src[k + 1]);
        float4 v0 = g_buf1[s0 * 16 + lane];
        float4 v1 = g_buf1[s1 * 16 + lane];
        acc.x += v0.x + v1.x; acc.y += v0.y + v1.y;
        acc.z += v0.z + v1.z; acc.w += v0.w + v1.w;
    }
    if (k < end) {
        int s = __ldg(&g_csr_src[k]);
        float4 v = g_buf1[s * 16 + lane];
        acc.x += v.x; acc.y += v.y; acc.z += v.z; acc.w += v.w;
    }
    float ni = g_norm_in[n];
    float4 b = ((const float4*)bias)[lane];
    float4 h;
    h.x = fmaxf(acc.x * ni + b.x, 0.f);
    h.y = fmaxf(acc.y * ni + b.y, 0.f);
    h.z = fmaxf(acc.z * ni + b.z, 0.f);
    h.w = fmaxf(acc.w * ni + b.w, 0.f);
    if (!FINAL) {
        g_buf2[n * 16 + lane] = h;
    } else {
        float4 a = ((const float4*)aW)[lane];
        float p = h.x * a.x + h.y * a.y + h.z * a.z + h.w * a.w;
#pragma unroll
        for (int o = 8; o; o >>= 1) p += __shfl_xor_sync(0xffffffffu, p, o, 16);
        float hw = 1.f / (1.f + __expf(-(p + __ldg(&ab[0]))));
        if (lane == 0) hw_out[n] = hw;
        float4 o4 = make_float4(h.x * hw, h.y * hw, h.z * hw, h.w * hw);
        g_buf2[n * 16 + lane] = o4;
    }
}

// ---------------------------------------------------------------------------
__global__ void pool_cls_kernel(const float* __restrict__ clsW,
                                const float* __restrict__ clsb,
                                float* __restrict__ out) {
    __shared__ float part[4][64];
    __shared__ float meanv[64];
    int g = blockIdx.x;
    int tid = threadIdx.x;
    int c = tid & 63, s = tid >> 6;
    int start = g_off[g], end = g_off[g + 1];
    float acc = 0.f;
    for (int n = start + s; n < end; n += 4)
        acc += ((const float*)g_buf2)[n * 64 + c];
    part[s][c] = acc;
    __syncthreads();
    if (s == 0) {
        float tot = part[0][c] + part[1][c] + part[2][c] + part[3][c];
        float cnt = fmaxf((float)(end - start), 1.f);
        meanv[c] = tot / cnt;
    }
    __syncthreads();
    if (tid < 10) {
        float a2 = __ldg(&clsb[tid]);
#pragma unroll
        for (int kk = 0; kk < 64; kk++)
            a2 += meanv[kk] * __ldg(&clsW[kk * 10 + tid]);
        out[g * 10 + tid] = a2;
    }
}

// ---------------------------------------------------------------------------
extern "C" void kernel_launch(void* const* d_in, const int* in_sizes, int n_in,
                              void* d_out, int out_size) {
    const float* x   = (const float*)d_in[0];
    const int*   ei  = (const int*)  d_in[1];
    const int*   gid = (const int*)  d_in[2];
    const float* W1  = (const float*)d_in[3];
    const float* b1  = (const float*)d_in[4];
    const float* W2  = (const float*)d_in[5];
    const float* b2  = (const float*)d_in[6];
    const float* aW  = (const float*)d_in[7];
    const float* ab  = (const float*)d_in[8];
    const float* cW  = (const float*)d_in[9];
    const float* cb  = (const float*)d_in[10];
    float* out = (float*)d_out;
    float* hw  = out + NG * 10;

    zero_kernel<<<(NN + 255) / 256, 256>>>();
    degree_kernel<<<(NE + 255) / 256, 256>>>(ei);
    scan1_kernel<<<NB, SBS>>>(gid);
    scan2_kernel<<<1, 32>>>();
    prefix_kernel<<<1, 32>>>();
    scan3_kernel<<<NB, SBS>>>();
    scatter_kernel<<<(NE + 255) / 256, 256>>>(ei);

    // Layer 1
    gemm_kernel<INDIM, false><<<(NN + 255) / 256, 256>>>(x, W1);
    spmm_kernel<false><<<(NN + 15) / 16, 256>>>(b1, nullptr, nullptr, nullptr);

    // Layer 2
    gemm_kernel<HID, true><<<(NN + 255) / 256, 256>>>(nullptr, W2);
    spmm_kernel<true><<<(NN + 15) / 16, 256>>>(b2, aW, ab, hw);

    // Readout
    pool_cls_kernel<<<NG, 256>>>(cW, cb, out);
}

// round 4
// speedup vs baseline: 2.1297x; 1.3488x over previous
#include <cuda_runtime.h>
#include <cuda_bf16.h>

#define NN 100000
#define NE 1600000
#define NG 64
#define HID 64
#define INDIM 128
#define SBS 512
#define NB ((NN + SBS - 1) / SBS)

// Scratch (__device__ globals per alloc-free rule)
__device__ float4 g_buf1[NN * 16];   // GEMM output scaled by norm_out (SpMM source)
__device__ float4 g_buf2[NN * 16];   // activations / gated output
__device__ float  g_norm_out[NN];
__device__ float  g_norm_in[NN];
__device__ int    g_deg_out[NN];
__device__ int    g_deg_in[NN];
__device__ int    g_fill[NN];
__device__ int    g_row_off[NN + 1];
__device__ int    g_csr_src[NE];
__device__ int    g_bsum[NB];
__device__ int    g_boff[NB];
__device__ int    g_cnt[NG];
__device__ int    g_off[NG + 1];

// ---------------------------------------------------------------------------
__global__ void zero_kernel() {
    int i = blockIdx.x * blockDim.x + threadIdx.x;
    if (i < NN) { g_deg_out[i] = 0; g_deg_in[i] = 0; g_fill[i] = 0; }
    if (i < NG) g_cnt[i] = 0;
}

__global__ void degree_kernel(const int* __restrict__ ei) {
    int e = blockIdx.x * blockDim.x + threadIdx.x;
    if (e < NE) {
        atomicAdd(&g_deg_out[ei[e]], 1);
        atomicAdd(&g_deg_in[ei[NE + e]], 1);
    }
}

// Per-block sums of deg_in (for scan) + graph-id histogram (sorted -> aggregated)
__global__ void scan1_kernel(const int* __restrict__ gid) {
    __shared__ int sh[SBS];
    int i = blockIdx.x * SBS + threadIdx.x;
    int v = (i < NN) ? g_deg_in[i] : 0;
    sh[threadIdx.x] = v;
    if (i < NN) atomicAdd(&g_cnt[gid[i]], 1);
    __syncthreads();
    for (int o = SBS / 2; o; o >>= 1) {
        if (threadIdx.x < o) sh[threadIdx.x] += sh[threadIdx.x + o];
        __syncthreads();
    }
    if (threadIdx.x == 0) g_bsum[blockIdx.x] = sh[0];
}

// Parallel scans of the 196 block sums AND the 64 graph counts (one kernel).
__global__ void scan_small_kernel() {
    __shared__ int sh[256];
    int t = threadIdx.x;
    int v = (t < NB) ? g_bsum[t] : 0;
    sh[t] = v;
    __syncthreads();
    for (int o = 1; o < 256; o <<= 1) {
        int u = (t >= o) ? sh[t - o] : 0;
        __syncthreads();
        sh[t] += u;
        __syncthreads();
    }
    if (t < NB) g_boff[t] = sh[t] - v;
    __syncthreads();
    int c = (t < NG) ? g_cnt[t] : 0;
    sh[t] = c;
    __syncthreads();
    for (int o = 1; o < 256; o <<= 1) {
        int u = (t >= o) ? sh[t - o] : 0;
        __syncthreads();
        sh[t] += u;
        __syncthreads();
    }
    if (t < NG) g_off[t] = sh[t] - c;
    if (t == 0) g_off[NG] = NN;
}

// Intra-block exclusive scan -> row offsets; also compute norms.
__global__ void scan3_kernel() {
    __shared__ int sh[SBS];
    int i = blockIdx.x * SBS + threadIdx.x;
    int v = (i < NN) ? g_deg_in[i] : 0;
    sh[threadIdx.x] = v;
    __syncthreads();
    for (int o = 1; o < SBS; o <<= 1) {
        int t = (threadIdx.x >= o) ? sh[threadIdx.x - o] : 0;
        __syncthreads();
        sh[threadIdx.x] += t;
        __syncthreads();
    }
    if (i < NN) {
        g_row_off[i] = g_boff[blockIdx.x] + sh[threadIdx.x] - v;
        g_norm_in[i]  = rsqrtf((float)max(v, 1));
        g_norm_out[i] = rsqrtf((float)max(g_deg_out[i], 1));
    }
    if (i == 0) g_row_off[NN] = NE;
}

__global__ void scatter_kernel(const int* __restrict__ ei) {
    int e = blockIdx.x * blockDim.x + threadIdx.x;
    if (e < NE) {
        int d = ei[NE + e];
        int pos = g_row_off[d] + atomicAdd(&g_fill[d], 1);
        g_csr_src[pos] = ei[e];
    }
}

// ---------------------------------------------------------------------------
// Register-tiled GEMM: buf1[n][c] = (X[n] @ W)[c] * norm_out[n].
// Block = 64 nodes x 64 cols, 256 threads, each thread a 4x4 register tile.
// K processed in 64-wide chunks (keeps static smem under 48KB).
// Inner loop per j: 1 LDS.128 (W, 4 cols) + 4 broadcast LDS.32 (X rows) -> 16 FFMA.
template <int IN, bool FROM_BUF2>
__global__ void gemm_kernel(const float* __restrict__ Xext,
                            const float* __restrict__ W) {
    __shared__ float Ws[64 * 64];        // one K-chunk of W: [64][64]
    __shared__ float Xs[64][68];         // one K-chunk of X: [node][j], pad 4
    const float* X = FROM_BUF2 ? (const float*)g_buf2 : Xext;
    int tid = threadIdx.x;
    int n0 = blockIdx.x * 64;
    int tx = tid & 15, ty = tid >> 4;
    int col = tx * 4, row = ty * 4;

    float4 acc0 = {0,0,0,0}, acc1 = {0,0,0,0}, acc2 = {0,0,0,0}, acc3 = {0,0,0,0};

#pragma unroll
    for (int kc = 0; kc < IN / 64; ++kc) {
        // Load W chunk: rows [kc*64, kc*64+64) of W[IN][64]
        {
            const float4* Wg = (const float4*)(W + kc * 64 * 64);
            for (int i = tid; i < 64 * 16; i += 256)
                ((float4*)Ws)[i] = Wg[i];
        }
        // Load X chunk: 64 nodes x 64 j's (float4-vectorized, coalesced)
        for (int i = tid; i < 64 * 16; i += 256) {
            int r = i >> 4, jv = i & 15;
            int n = n0 + r;
            float4 v = (n < NN)
                ? ((const float4*)(X + (size_t)n * IN + kc * 64))[jv]
                : make_float4(0.f, 0.f, 0.f, 0.f);
            *(float4*)&Xs[r][jv * 4] = v;
        }
        __syncthreads();
#pragma unroll 4
        for (int j = 0; j < 64; ++j) {
            float4 w = *(const float4*)&Ws[j * 64 + col];
            float x0 = Xs[row + 0][j];
            float x1 = Xs[row + 1][j];
            float x2 = Xs[row + 2][j];
            float x3 = Xs[row + 3][j];
            acc0.x += x0 * w.x; acc0.y += x0 * w.y; acc0.z += x0 * w.z; acc0.w += x0 * w.w;
            acc1.x += x1 * w.x; acc1.y += x1 * w.y; acc1.z += x1 * w.z; acc1.w += x1 * w.w;
            acc2.x += x2 * w.x; acc2.y += x2 * w.y; acc2.z += x2 * w.z; acc2.w += x2 * w.w;
            acc3.x += x3 * w.x; acc3.y += x3 * w.y; acc3.z += x3 * w.z; acc3.w += x3 * w.w;
        }
        __syncthreads();
    }

    float* B1 = (float*)g_buf1;
    float4 accs[4] = {acc0, acc1, acc2, acc3};
#pragma unroll
    for (int r = 0; r < 4; ++r) {
        int n = n0 + row + r;
        if (n < NN) {
            float no = g_norm_out[n];
            float4 o = accs[r];
            o.x *= no; o.y *= no; o.z *= no; o.w *= no;
            *(float4*)&B1[(size_t)n * 64 + col] = o;
        }
    }
}

// ---------------------------------------------------------------------------
// CSR SpMM + fused epilogue. 16 lanes per dst node (one float4 col-chunk/lane),
// register accumulation, 4-way ILP on the neighbor gather.
template <bool FINAL>
__global__ void spmm_kernel(const float* __restrict__ bias,
                            const float* __restrict__ aW,
                            const float* __restrict__ ab,
                            float* __restrict__ hw_out) {
    int tid = threadIdx.x;
    int n = blockIdx.x * 16 + (tid >> 4);
    if (n >= NN) return;
    int lane = tid & 15;
    int beg = g_row_off[n], end = g_row_off[n + 1];
    float4 acc = make_float4(0.f, 0.f, 0.f, 0.f);
    int k = beg;
    for (; k + 4 <= end; k += 4) {
        int s0 = __ldg(&g_csr_src[k]);
        int s1 = __ldg(&g_csr_src[k + 1]);
        int s2 = __ldg(&g_csr_src[k + 2]);
        int s3 = __ldg(&g_csr_src[k + 3]);
        float4 v0 = g_buf1[s0 * 16 + lane];
        float4 v1 = g_buf1[s1 * 16 + lane];
        float4 v2 = g_buf1[s2 * 16 + lane];
        float4 v3 = g_buf1[s3 * 16 + lane];
        acc.x += (v0.x + v1.x) + (v2.x + v3.x);
        acc.y += (v0.y + v1.y) + (v2.y + v3.y);
        acc.z += (v0.z + v1.z) + (v2.z + v3.z);
        acc.w += (v0.w + v1.w) + (v2.w + v3.w);
    }
    for (; k < end; ++k) {
        int s = __ldg(&g_csr_src[k]);
        float4 v = g_buf1[s * 16 + lane];
        acc.x += v.x; acc.y += v.y; acc.z += v.z; acc.w += v.w;
    }
    float ni = g_norm_in[n];
    float4 b = ((const float4*)bias)[lane];
    float4 h;
    h.x = fmaxf(acc.x * ni + b.x, 0.f);
    h.y = fmaxf(acc.y * ni + b.y, 0.f);
    h.z = fmaxf(acc.z * ni + b.z, 0.f);
    h.w = fmaxf(acc.w * ni + b.w, 0.f);
    if (!FINAL) {
        g_buf2[n * 16 + lane] = h;
    } else {
        float4 a = ((const float4*)aW)[lane];
        float p = h.x * a.x + h.y * a.y + h.z * a.z + h.w * a.w;
#pragma unroll
        for (int o = 8; o; o >>= 1) p += __shfl_xor_sync(0xffffffffu, p, o, 16);
        float hw = 1.f / (1.f + __expf(-(p + __ldg(&ab[0]))));
        if (lane == 0) hw_out[n] = hw;
        float4 o4 = make_float4(h.x * hw, h.y * hw, h.z * hw, h.w * hw);
        g_buf2[n * 16 + lane] = o4;
    }
}

// ---------------------------------------------------------------------------
__global__ void pool_cls_kernel(const float* __restrict__ clsW,
                                const float* __restrict__ clsb,
                                float* __restrict__ out) {
    __shared__ float part[8][64];
    __shared__ float meanv[64];
    int g = blockIdx.x;
    int tid = threadIdx.x;
    int c = tid & 63, s = tid >> 6;
    int start = g_off[g], end = g_off[g + 1];
    float acc = 0.f;
    for (int n = start + s; n < end; n += 8)
        acc += ((const float*)g_buf2)[(size_t)n * 64 + c];
    part[s][c] = acc;
    __syncthreads();
    if (s == 0) {
        float tot = 0.f;
#pragma unroll
        for (int q = 0; q < 8; q++) tot += part[q][c];
        float cnt = fmaxf((float)(end - start), 1.f);
        meanv[c] = tot / cnt;
    }
    __syncthreads();
    if (tid < 10) {
        float a2 = __ldg(&clsb[tid]);
#pragma unroll
        for (int kk = 0; kk < 64; kk++)
            a2 += meanv[kk] * __ldg(&clsW[kk * 10 + tid]);
        out[g * 10 + tid] = a2;
    }
}

// ---------------------------------------------------------------------------
extern "C" void kernel_launch(void* const* d_in, const int* in_sizes, int n_in,
                              void* d_out, int out_size) {
    const float* x   = (const float*)d_in[0];
    const int*   ei  = (const int*)  d_in[1];
    const int*   gid = (const int*)  d_in[2];
    const float* W1  = (const float*)d_in[3];
    const float* b1  = (const float*)d_in[4];
    const float* W2  = (const float*)d_in[5];
    const float* b2  = (const float*)d_in[6];
    const float* aW  = (const float*)d_in[7];
    const float* ab  = (const float*)d_in[8];
    const float* cW  = (const float*)d_in[9];
    const float* cb  = (const float*)d_in[10];
    float* out = (float*)d_out;
    float* hw  = out + NG * 10;

    zero_kernel<<<(NN + 255) / 256, 256>>>();
    degree_kernel<<<(NE + 255) / 256, 256>>>(ei);
    scan1_kernel<<<NB, SBS>>>(gid);
    scan_small_kernel<<<1, 256>>>();
    scan3_kernel<<<NB, SBS>>>();
    scatter_kernel<<<(NE + 255) / 256, 256>>>(ei);

    // Layer 1
    gemm_kernel<INDIM, false><<<(NN + 63) / 64, 256>>>(x, W1);
    spmm_kernel<false><<<(NN + 15) / 16, 256>>>(b1, nullptr, nullptr, nullptr);

    // Layer 2
    gemm_kernel<HID, true><<<(NN + 63) / 64, 256>>>(nullptr, W2);
    spmm_kernel<true><<<(NN + 15) / 16, 256>>>(b2, aW, ab, hw);

    // Readout
    pool_cls_kernel<<<NG, 512>>>(cW, cb, out);
}

// round 7
// speedup vs baseline: 2.2790x; 1.0701x over previous
#include <cuda_runtime.h>
#include <cuda_bf16.h>
#include <cuda_fp16.h>
#include <cstdint>

#define NN 100000
#define NE 1600000
#define NG 64
#define HID 64
#define INDIM 128
#define SBS 512
#define NB ((NN + SBS - 1) / SBS)

// Scratch (__device__ globals per alloc-free rule)
__device__ float4 g_buf1[NN * 16];   // GEMM output scaled by norm_out (SpMM source)
__device__ float4 g_buf2[NN * 16];   // activations / gated output
__device__ float  g_norm_out[NN];
__device__ float  g_norm_in[NN];
__device__ int    g_deg_out[NN];
__device__ int    g_deg_in[NN];
__device__ int    g_fill[NN];
__device__ int    g_row_off[NN + 1];
__device__ int    g_csr_src[NE];
__device__ int    g_bsum[NB];
__device__ int    g_boff[NB];
__device__ int    g_cnt[NG];
__device__ int    g_off[NG + 1];

// ---------------------------------------------------------------------------
__device__ __forceinline__ uint32_t smem_u32(const void* p) {
    uint32_t a;
    asm("{ .reg .u64 t; cvta.to.shared.u64 t, %1; cvt.u32.u64 %0, t; }"
        : "=r"(a) : "l"(p));
    return a;
}
__device__ __forceinline__ void ldm_x4(uint32_t* r, uint32_t addr) {
    asm volatile("ldmatrix.sync.aligned.m8n8.x4.shared.b16 {%0,%1,%2,%3}, [%4];"
                 : "=r"(r[0]), "=r"(r[1]), "=r"(r[2]), "=r"(r[3]) : "r"(addr));
}
__device__ __forceinline__ void mma_16816(float* d, const uint32_t* a,
                                          const uint32_t* b) {
    asm volatile("mma.sync.aligned.m16n8k16.row.col.f32.f16.f16.f32 "
                 "{%0,%1,%2,%3}, {%4,%5,%6,%7}, {%8,%9}, {%0,%1,%2,%3};"
                 : "+f"(d[0]), "+f"(d[1]), "+f"(d[2]), "+f"(d[3])
                 : "r"(a[0]), "r"(a[1]), "r"(a[2]), "r"(a[3]),
                   "r"(b[0]), "r"(b[1]));
}

// ---------------------------------------------------------------------------
__global__ void zero_kernel() {
    int i = blockIdx.x * blockDim.x + threadIdx.x;
    if (i < NN) { g_deg_out[i] = 0; g_deg_in[i] = 0; }
    if (i < NG) g_cnt[i] = 0;
}

__global__ void degree_kernel(const int* __restrict__ ei) {
    int e = blockIdx.x * blockDim.x + threadIdx.x;
    if (e < NE) {
        atomicAdd(&g_deg_out[ei[e]], 1);
        atomicAdd(&g_deg_in[ei[NE + e]], 1);
    }
}

__global__ void scan1_kernel(const int* __restrict__ gid) {
    __shared__ int sh[SBS];
    int i = blockIdx.x * SBS + threadIdx.x;
    int v = (i < NN) ? g_deg_in[i] : 0;
    sh[threadIdx.x] = v;
    if (i < NN) atomicAdd(&g_cnt[gid[i]], 1);
    __syncthreads();
    for (int o = SBS / 2; o; o >>= 1) {
        if (threadIdx.x < o) sh[threadIdx.x] += sh[threadIdx.x + o];
        __syncthreads();
    }
    if (threadIdx.x == 0) g_bsum[blockIdx.x] = sh[0];
}

__global__ void scan_small_kernel() {
    __shared__ int sh[256];
    int t = threadIdx.x;
    int v = (t < NB) ? g_bsum[t] : 0;
    sh[t] = v;
    __syncthreads();
    for (int o = 1; o < 256; o <<= 1) {
        int u = (t >= o) ? sh[t - o] : 0;
        __syncthreads();
        sh[t] += u;
        __syncthreads();
    }
    if (t < NB) g_boff[t] = sh[t] - v;
    __syncthreads();
    int c = (t < NG) ? g_cnt[t] : 0;
    sh[t] = c;
    __syncthreads();
    for (int o = 1; o < 256; o <<= 1) {
        int u = (t >= o) ? sh[t - o] : 0;
        __syncthreads();
        sh[t] += u;
        __syncthreads();
    }
    if (t < NG) g_off[t] = sh[t] - c;
    if (t == 0) g_off[NG] = NN;
}

__global__ void scan3_kernel() {
    __shared__ int sh[SBS];
    int i = blockIdx.x * SBS + threadIdx.x;
    int v = (i < NN) ? g_deg_in[i] : 0;
    sh[threadIdx.x] = v;
    __syncthreads();
    for (int o = 1; o < SBS; o <<= 1) {
        int t = (threadIdx.x >= o) ? sh[threadIdx.x - o] : 0;
        __syncthreads();
        sh[threadIdx.x] += t;
        __syncthreads();
    }
    if (i < NN) {
        int ro = g_boff[blockIdx.x] + sh[threadIdx.x] - v;
        g_row_off[i] = ro;
        g_fill[i] = ro;
        g_norm_in[i]  = rsqrtf((float)max(v, 1));
        g_norm_out[i] = rsqrtf((float)max(g_deg_out[i], 1));
    }
    if (i == 0) g_row_off[NN] = NE;
}

__global__ void scatter_kernel(const int* __restrict__ ei) {
    int e = blockIdx.x * blockDim.x + threadIdx.x;
    if (e < NE) {
        int d = ei[NE + e];
        int pos = atomicAdd(&g_fill[d], 1);
        g_csr_src[pos] = ei[e];
    }
}

// ---------------------------------------------------------------------------
// HMMA GEMM: buf1[n][c] = (X[n] @ W)[c] * norm_out[n].
// fp32 -> fp16 hi/lo split: D = Ah*Bh + Ah*Bl + Al*Bh (fp32 accumulators).
// Block: 128 nodes x 64 cols, 8 warps (4 M x 2 N), warp tile 32x32,
// mma.m16n8k16 fragments (2 m-subtiles x 4 n-subtiles). K chunked by 64.
// SMEM (dynamic 54KB): Ah/Al [128][72] half, Bh/Bl = W^T [64][72] half.
#define APAD 72
template <int K, bool FROM_BUF2>
__global__ void __launch_bounds__(256)
gemm_mma_kernel(const float* __restrict__ Xext, const float* __restrict__ W) {
    extern __shared__ __half sm[];
    __half* Ah = sm;
    __half* Al = Ah + 128 * APAD;
    __half* Bh = Al + 128 * APAD;
    __half* Bl = Bh + 64 * APAD;
    const float* X = FROM_BUF2 ? (const float*)g_buf2 : Xext;

    int tid = threadIdx.x;
    int warp = tid >> 5, lane = tid & 31;
    int wm = warp & 3, wn = warp >> 2;      // warp tile: rows wm*32, cols wn*32
    int n0 = blockIdx.x * 128;

    float d[2][4][4];
#pragma unroll
    for (int mt = 0; mt < 2; ++mt)
#pragma unroll
        for (int nt = 0; nt < 4; ++nt)
#pragma unroll
            for (int q = 0; q < 4; ++q) d[mt][nt][q] = 0.f;

#pragma unroll
    for (int kc = 0; kc < K / 64; ++kc) {
        // Stage A: 128 rows x 64 k (float4 loads, hi/lo split)
        for (int i = tid; i < 128 * 16; i += 256) {
            int r = i >> 4, jv = i & 15;
            int n = n0 + r;
            float4 v = (n < NN)
                ? __ldg((const float4*)(X + (size_t)n * K + kc * 64) + jv)
                : make_float4(0.f, 0.f, 0.f, 0.f);
            float vv[4] = {v.x, v.y, v.z, v.w};
#pragma unroll
            for (int e = 0; e < 4; ++e) {
                __half h = __float2half_rn(vv[e]);
                __half l = __float2half_rn(vv[e] - __half2float(h));
                Ah[r * APAD + jv * 4 + e] = h;
                Al[r * APAD + jv * 4 + e] = l;
            }
        }
        // Stage B = W^T chunk: Bt[n][k] = W[(kc*64+k)*64 + n]
        for (int i = tid; i < 64 * 64; i += 256) {
            int k = i >> 6, n = i & 63;
            float w = __ldg(&W[(kc * 64 + k) * 64 + n]);
            __half h = __float2half_rn(w);
            __half l = __float2half_rn(w - __half2float(h));
            Bh[n * APAD + k] = h;
            Bl[n * APAD + k] = l;
        }
        __syncthreads();

#pragma unroll
        for (int ks = 0; ks < 4; ++ks) {
            uint32_t ah[2][4], al[2][4], bh[4][2], bl[4][2];
#pragma unroll
            for (int mt = 0; mt < 2; ++mt) {
                int row = wm * 32 + mt * 16 + (lane & 15);
                int col = ks * 16 + (lane >> 4) * 8;
                ldm_x4(ah[mt], smem_u32(&Ah[row * APAD + col]));
                ldm_x4(al[mt], smem_u32(&Al[row * APAD + col]));
            }
            int k0 = ks * 16 + (lane & 3) * 2;
#pragma unroll
            for (int nt = 0; nt < 4; ++nt) {
                int n = wn * 32 + nt * 8 + (lane >> 2);
                bh[nt][0] = *(const uint32_t*)&Bh[n * APAD + k0];
                bh[nt][1] = *(const uint32_t*)&Bh[n * APAD + k0 + 8];
                bl[nt][0] = *(const uint32_t*)&Bl[n * APAD + k0];
                bl[nt][1] = *(const uint32_t*)&Bl[n * APAD + k0 + 8];
            }
#pragma unroll
            for (int mt = 0; mt < 2; ++mt)
#pragma unroll
                for (int nt = 0; nt < 4; ++nt) {
                    mma_16816(d[mt][nt], ah[mt], bh[nt]);
                    mma_16816(d[mt][nt], ah[mt], bl[nt]);
                    mma_16816(d[mt][nt], al[mt], bh[nt]);
                }
        }
        __syncthreads();
    }

    // Epilogue: scale rows by norm_out, write buf1 (float2 stores)
    float* B1 = (float*)g_buf1;
#pragma unroll
    for (int mt = 0; mt < 2; ++mt) {
        int r0 = n0 + wm * 32 + mt * 16 + (lane >> 2);
        int r1 = r0 + 8;
        float s0 = (r0 < NN) ? g_norm_out[r0] : 0.f;
        float s1 = (r1 < NN) ? g_norm_out[r1] : 0.f;
#pragma unroll
        for (int nt = 0; nt < 4; ++nt) {
            int c = wn * 32 + nt * 8 + (lane & 3) * 2;
            if (r0 < NN) {
                float2 o = {d[mt][nt][0] * s0, d[mt][nt][1] * s0};
                *(float2*)&B1[(size_t)r0 * 64 + c] = o;
            }
            if (r1 < NN) {
                float2 o = {d[mt][nt][2] * s1, d[mt][nt][3] * s1};
                *(float2*)&B1[(size_t)r1 * 64 + c] = o;
            }
        }
    }
}
#define GEMM_SMEM ((2 * 128 * APAD + 2 * 64 * APAD) * 2)

// ---------------------------------------------------------------------------
// CSR SpMM + fused epilogue. 16 lanes per dst node, register accumulation.
template <bool FINAL>
__global__ void spmm_kernel(const float* __restrict__ bias,
                            const float* __restrict__ aW,
                            const float* __restrict__ ab,
                            float* __restrict__ hw_out) {
    int tid = threadIdx.x;
    int n = blockIdx.x * 16 + (tid >> 4);
    if (n >= NN) return;
    int lane = tid & 15;
    int beg = g_row_off[n], end = g_row_off[n + 1];
    float4 acc = make_float4(0.f, 0.f, 0.f, 0.f);
    int k = beg;
    for (; k + 4 <= end; k += 4) {
        int s0 = __ldg(&g_csr_src[k]);
        int s1 = __ldg(&g_csr_src[k + 1]);
        int s2 = __ldg(&g_csr_src[k + 2]);
        int s3 = __ldg(&g_csr_src[k + 3]);
        float4 v0 = g_buf1[s0 * 16 + lane];
        float4 v1 = g_buf1[s1 * 16 + lane];
        float4 v2 = g_buf1[s2 * 16 + lane];
        float4 v3 = g_buf1[s3 * 16 + lane];
        acc.x += (v0.x + v1.x) + (v2.x + v3.x);
        acc.y += (v0.y + v1.y) + (v2.y + v3.y);
        acc.z += (v0.z + v1.z) + (v2.z + v3.z);
        acc.w += (v0.w + v1.w) + (v2.w + v3.w);
    }
    for (; k < end; ++k) {
        int s = __ldg(&g_csr_src[k]);
        float4 v = g_buf1[s * 16 + lane];
        acc.x += v.x; acc.y += v.y; acc.z += v.z; acc.w += v.w;
    }
    float ni = g_norm_in[n];
    float4 b = ((const float4*)bias)[lane];
    float4 h;
    h.x = fmaxf(acc.x * ni + b.x, 0.f);
    h.y = fmaxf(acc.y * ni + b.y, 0.f);
    h.z = fmaxf(acc.z * ni + b.z, 0.f);
    h.w = fmaxf(acc.w * ni + b.w, 0.f);
    if (!FINAL) {
        g_buf2[n * 16 + lane] = h;
    } else {
        float4 a = ((const float4*)aW)[lane];
        float p = h.x * a.x + h.y * a.y + h.z * a.z + h.w * a.w;
#pragma unroll
        for (int o = 8; o; o >>= 1) p += __shfl_xor_sync(0xffffffffu, p, o, 16);
        float hw = 1.f / (1.f + __expf(-(p + __ldg(&ab[0]))));
        if (lane == 0) hw_out[n] = hw;
        float4 o4 = make_float4(h.x * hw, h.y * hw, h.z * hw, h.w * hw);
        g_buf2[n * 16 + lane] = o4;
    }
}

// ---------------------------------------------------------------------------
__global__ void pool_cls_kernel(const float* __restrict__ clsW,
                                const float* __restrict__ clsb,
                                float* __restrict__ out) {
    __shared__ float part[8][64];
    __shared__ float meanv[64];
    int g = blockIdx.x;
    int tid = threadIdx.x;
    int c = tid & 63, s = tid >> 6;
    int start = g_off[g], end = g_off[g + 1];
    float acc = 0.f;
    for (int n = start + s; n < end; n += 8)
        acc += ((const float*)g_buf2)[(size_t)n * 64 + c];
    part[s][c] = acc;
    __syncthreads();
    if (s == 0) {
        float tot = 0.f;
#pragma unroll
        for (int q = 0; q < 8; q++) tot += part[q][c];
        float cnt = fmaxf((float)(end - start), 1.f);
        meanv[c] = tot / cnt;
    }
    __syncthreads();
    if (tid < 10) {
        float a2 = __ldg(&clsb[tid]);
#pragma unroll
        for (int kk = 0; kk < 64; kk++)
            a2 += meanv[kk] * __ldg(&clsW[kk * 10 + tid]);
        out[g * 10 + tid] = a2;
    }
}

// ---------------------------------------------------------------------------
extern "C" void kernel_launch(void* const* d_in, const int* in_sizes, int n_in,
                              void* d_out, int out_size) {
    const float* x   = (const float*)d_in[0];
    const int*   ei  = (const int*)  d_in[1];
    const int*   gid = (const int*)  d_in[2];
    const float* W1  = (const float*)d_in[3];
    const float* b1  = (const float*)d_in[4];
    const float* W2  = (const float*)d_in[5];
    const float* b2  = (const float*)d_in[6];
    const float* aW  = (const float*)d_in[7];
    const float* ab  = (const float*)d_in[8];
    const float* cW  = (const float*)d_in[9];
    const float* cb  = (const float*)d_in[10];
    float* out = (float*)d_out;
    float* hw  = out + NG * 10;

    static bool attr_done = false;
    if (!attr_done) {
        cudaFuncSetAttribute(gemm_mma_kernel<INDIM, false>,
                             cudaFuncAttributeMaxDynamicSharedMemorySize, GEMM_SMEM);
        cudaFuncSetAttribute(gemm_mma_kernel<HID, true>,
                             cudaFuncAttributeMaxDynamicSharedMemorySize, GEMM_SMEM);
        attr_done = true;
    }

    zero_kernel<<<(NN + 255) / 256, 256>>>();
    degree_kernel<<<(NE + 255) / 256, 256>>>(ei);
    scan1_kernel<<<NB, SBS>>>(gid);
    scan_small_kernel<<<1, 256>>>();
    scan3_kernel<<<NB, SBS>>>();
    scatter_kernel<<<(NE + 255) / 256, 256>>>(ei);

    // Layer 1
    gemm_mma_kernel<INDIM, false><<<(NN + 127) / 128, 256, GEMM_SMEM>>>(x, W1);
    spmm_kernel<false><<<(NN + 15) / 16, 256>>>(b1, nullptr, nullptr, nullptr);

    // Layer 2
    gemm_mma_kernel<HID, true><<<(NN + 127) / 128, 256, GEMM_SMEM>>>(nullptr, W2);
    spmm_kernel<true><<<(NN + 15) / 16, 256>>>(b2, aW, ab, hw);

    // Readout
    pool_cls_kernel<<<NG, 512>>>(cW, cb, out);
}

// round 8
// speedup vs baseline: 2.6817x; 1.1767x over previous
#include <cuda_runtime.h>
#include <cuda_bf16.h>
#include <cuda_fp16.h>
#include <cstdint>

#define NN 100000
#define NE 1600000
#define NG 64
#define HID 64
#define INDIM 128

// Scratch (__device__ globals per alloc-free rule)
__device__ float4 g_buf1[NN * 16];   // GEMM output scaled by norm_out (SpMM source)
__device__ float4 g_buf2[NN * 16];   // activations / gated output
__device__ float  g_norm_out[NN];
__device__ float  g_norm_in[NN];
__device__ int    g_deg_out[NN];
__device__ int    g_deg_in[NN];
__device__ int    g_fill[NN];
__device__ int    g_row_off[NN];
__device__ int    g_csr_src[NE];
__device__ int    g_total;
__device__ int    g_off[NG + 1];

// ---------------------------------------------------------------------------
__device__ __forceinline__ uint32_t smem_u32(const void* p) {
    uint32_t a;
    asm("{ .reg .u64 t; cvta.to.shared.u64 t, %1; cvt.u32.u64 %0, t; }"
        : "=r"(a) : "l"(p));
    return a;
}
__device__ __forceinline__ void ldm_x4(uint32_t* r, uint32_t addr) {
    asm volatile("ldmatrix.sync.aligned.m8n8.x4.shared.b16 {%0,%1,%2,%3}, [%4];"
                 : "=r"(r[0]), "=r"(r[1]), "=r"(r[2]), "=r"(r[3]) : "r"(addr));
}
__device__ __forceinline__ void mma_16816(float* d, const uint32_t* a,
                                          const uint32_t* b) {
    asm volatile("mma.sync.aligned.m16n8k16.row.col.f32.f16.f16.f32 "
                 "{%0,%1,%2,%3}, {%4,%5,%6,%7}, {%8,%9}, {%0,%1,%2,%3};"
                 : "+f"(d[0]), "+f"(d[1]), "+f"(d[2]), "+f"(d[3])
                 : "r"(a[0]), "r"(a[1]), "r"(a[2]), "r"(a[3]),
                   "r"(b[0]), "r"(b[1]));
}

// ---------------------------------------------------------------------------
__global__ void zero_kernel() {
    int i = blockIdx.x * blockDim.x + threadIdx.x;
    if (i < NN) { g_deg_out[i] = 0; g_deg_in[i] = 0; }
    if (i == 0) g_total = 0;
}

__global__ void degree_kernel(const int* __restrict__ ei) {
    int e = blockIdx.x * blockDim.x + threadIdx.x;
    if (e < NE) {
        atomicAdd(&g_deg_out[ei[e]], 1);
        atomicAdd(&g_deg_in[ei[NE + e]], 1);
    }
}

// Bump-allocated CSR segments (order-free) + both norms, one pass.
__global__ void norm_off_kernel() {
    int i = blockIdx.x * blockDim.x + threadIdx.x;
    if (i < NN) {
        int deg = g_deg_in[i];
        int ro = atomicAdd(&g_total, deg);
        g_row_off[i] = ro;
        g_fill[i] = ro;
        g_norm_in[i]  = rsqrtf((float)max(deg, 1));
        g_norm_out[i] = rsqrtf((float)max(g_deg_out[i], 1));
    }
}

// graph_id is sorted: segment starts via binary search (1 block, 65 threads used)
__global__ void graph_bounds_kernel(const int* __restrict__ gid) {
    int t = threadIdx.x;
    if (t > NG) return;
    int lo = 0, hi = NN;            // smallest i with gid[i] >= t
    while (lo < hi) {
        int mid = (lo + hi) >> 1;
        if (__ldg(&gid[mid]) < t) lo = mid + 1; else hi = mid;
    }
    g_off[t] = lo;
}

__global__ void scatter_kernel(const int* __restrict__ ei) {
    int e = blockIdx.x * blockDim.x + threadIdx.x;
    if (e < NE) {
        int d = ei[NE + e];
        int pos = atomicAdd(&g_fill[d], 1);
        g_csr_src[pos] = ei[e];
    }
}

// ---------------------------------------------------------------------------
// HMMA GEMM: buf1[n][c] = (X[n] @ W)[c] * norm_out[n].
// fp32 -> fp16 hi/lo split: D = Ah*Bh + Ah*Bl + Al*Bh (fp32 accumulators).
#define APAD 72
template <int K, bool FROM_BUF2>
__global__ void __launch_bounds__(256)
gemm_mma_kernel(const float* __restrict__ Xext, const float* __restrict__ W) {
    extern __shared__ __half sm[];
    __half* Ah = sm;
    __half* Al = Ah + 128 * APAD;
    __half* Bh = Al + 128 * APAD;
    __half* Bl = Bh + 64 * APAD;
    const float* X = FROM_BUF2 ? (const float*)g_buf2 : Xext;

    int tid = threadIdx.x;
    int warp = tid >> 5, lane = tid & 31;
    int wm = warp & 3, wn = warp >> 2;
    int n0 = blockIdx.x * 128;

    float d[2][4][4];
#pragma unroll
    for (int mt = 0; mt < 2; ++mt)
#pragma unroll
        for (int nt = 0; nt < 4; ++nt)
#pragma unroll
            for (int q = 0; q < 4; ++q) d[mt][nt][q] = 0.f;

#pragma unroll
    for (int kc = 0; kc < K / 64; ++kc) {
        for (int i = tid; i < 128 * 16; i += 256) {
            int r = i >> 4, jv = i & 15;
            int n = n0 + r;
            float4 v = (n < NN)
                ? __ldg((const float4*)(X + (size_t)n * K + kc * 64) + jv)
                : make_float4(0.f, 0.f, 0.f, 0.f);
            float vv[4] = {v.x, v.y, v.z, v.w};
#pragma unroll
            for (int e = 0; e < 4; ++e) {
                __half h = __float2half_rn(vv[e]);
                __half l = __float2half_rn(vv[e] - __half2float(h));
                Ah[r * APAD + jv * 4 + e] = h;
                Al[r * APAD + jv * 4 + e] = l;
            }
        }
        for (int i = tid; i < 64 * 64; i += 256) {
            int k = i >> 6, n = i & 63;
            float w = __ldg(&W[(kc * 64 + k) * 64 + n]);
            __half h = __float2half_rn(w);
            __half l = __float2half_rn(w - __half2float(h));
            Bh[n * APAD + k] = h;
            Bl[n * APAD + k] = l;
        }
        __syncthreads();

#pragma unroll
        for (int ks = 0; ks < 4; ++ks) {
            uint32_t ah[2][4], al[2][4], bh[4][2], bl[4][2];
#pragma unroll
            for (int mt = 0; mt < 2; ++mt) {
                int row = wm * 32 + mt * 16 + (lane & 15);
                int col = ks * 16 + (lane >> 4) * 8;
                ldm_x4(ah[mt], smem_u32(&Ah[row * APAD + col]));
                ldm_x4(al[mt], smem_u32(&Al[row * APAD + col]));
            }
            int k0 = ks * 16 + (lane & 3) * 2;
#pragma unroll
            for (int nt = 0; nt < 4; ++nt) {
                int n = wn * 32 + nt * 8 + (lane >> 2);
                bh[nt][0] = *(const uint32_t*)&Bh[n * APAD + k0];
                bh[nt][1] = *(const uint32_t*)&Bh[n * APAD + k0 + 8];
                bl[nt][0] = *(const uint32_t*)&Bl[n * APAD + k0];
                bl[nt][1] = *(const uint32_t*)&Bl[n * APAD + k0 + 8];
            }
#pragma unroll
            for (int mt = 0; mt < 2; ++mt)
#pragma unroll
                for (int nt = 0; nt < 4; ++nt) {
                    mma_16816(d[mt][nt], ah[mt], bh[nt]);
                    mma_16816(d[mt][nt], ah[mt], bl[nt]);
                    mma_16816(d[mt][nt], al[mt], bh[nt]);
                }
        }
        __syncthreads();
    }

    float* B1 = (float*)g_buf1;
#pragma unroll
    for (int mt = 0; mt < 2; ++mt) {
        int r0 = n0 + wm * 32 + mt * 16 + (lane >> 2);
        int r1 = r0 + 8;
        float s0 = (r0 < NN) ? g_norm_out[r0] : 0.f;
        float s1 = (r1 < NN) ? g_norm_out[r1] : 0.f;
#pragma unroll
        for (int nt = 0; nt < 4; ++nt) {
            int c = wn * 32 + nt * 8 + (lane & 3) * 2;
            if (r0 < NN) {
                float2 o = {d[mt][nt][0] * s0, d[mt][nt][1] * s0};
                *(float2*)&B1[(size_t)r0 * 64 + c] = o;
            }
            if (r1 < NN) {
                float2 o = {d[mt][nt][2] * s1, d[mt][nt][3] * s1};
                *(float2*)&B1[(size_t)r1 * 64 + c] = o;
            }
        }
    }
}
#define GEMM_SMEM ((2 * 128 * APAD + 2 * 64 * APAD) * 2)

// ---------------------------------------------------------------------------
// CSR SpMM + fused epilogue. One warp per dst node, float2 per lane,
// register accumulation, 4-way ILP. No intra-warp degree divergence.
template <bool FINAL>
__global__ void spmm_kernel(const float* __restrict__ bias,
                            const float* __restrict__ aW,
                            const float* __restrict__ ab,
                            float* __restrict__ hw_out) {
    int n = blockIdx.x * 8 + (threadIdx.x >> 5);
    if (n >= NN) return;
    int lane = threadIdx.x & 31;
    int beg = g_row_off[n];
    int end = beg + g_deg_in[n];
    const float2* B1 = (const float2*)g_buf1;   // row stride 32 float2
    float2 acc = make_float2(0.f, 0.f);
    int k = beg;
    for (; k + 4 <= end; k += 4) {
        int s0 = __ldg(&g_csr_src[k]);
        int s1 = __ldg(&g_csr_src[k + 1]);
        int s2 = __ldg(&g_csr_src[k + 2]);
        int s3 = __ldg(&g_csr_src[k + 3]);
        float2 v0 = B1[(size_t)s0 * 32 + lane];
        float2 v1 = B1[(size_t)s1 * 32 + lane];
        float2 v2 = B1[(size_t)s2 * 32 + lane];
        float2 v3 = B1[(size_t)s3 * 32 + lane];
        acc.x += (v0.x + v1.x) + (v2.x + v3.x);
        acc.y += (v0.y + v1.y) + (v2.y + v3.y);
    }
    for (; k < end; ++k) {
        int s = __ldg(&g_csr_src[k]);
        float2 v = B1[(size_t)s * 32 + lane];
        acc.x += v.x; acc.y += v.y;
    }
    float ni = g_norm_in[n];
    float2 b = ((const float2*)bias)[lane];
    float2 h;
    h.x = fmaxf(acc.x * ni + b.x, 0.f);
    h.y = fmaxf(acc.y * ni + b.y, 0.f);
    float2* B2 = (float2*)g_buf2;
    if (!FINAL) {
        B2[(size_t)n * 32 + lane] = h;
    } else {
        float2 a = ((const float2*)aW)[lane];
        float p = h.x * a.x + h.y * a.y;
#pragma unroll
        for (int o = 16; o; o >>= 1) p += __shfl_xor_sync(0xffffffffu, p, o);
        float hw = 1.f / (1.f + __expf(-(p + __ldg(&ab[0]))));
        if (lane == 0) hw_out[n] = hw;
        B2[(size_t)n * 32 + lane] = make_float2(h.x * hw, h.y * hw);
    }
}

// ---------------------------------------------------------------------------
__global__ void pool_cls_kernel(const float* __restrict__ clsW,
                                const float* __restrict__ clsb,
                                float* __restrict__ out) {
    __shared__ float part[8][64];
    __shared__ float meanv[64];
    int g = blockIdx.x;
    int tid = threadIdx.x;
    int c = tid & 63, s = tid >> 6;
    int start = g_off[g], end = g_off[g + 1];
    float acc = 0.f;
    for (int n = start + s; n < end; n += 8)
        acc += ((const float*)g_buf2)[(size_t)n * 64 + c];
    part[s][c] = acc;
    __syncthreads();
    if (s == 0) {
        float tot = 0.f;
#pragma unroll
        for (int q = 0; q < 8; q++) tot += part[q][c];
        float cnt = fmaxf((float)(end - start), 1.f);
        meanv[c] = tot / cnt;
    }
    __syncthreads();
    if (tid < 10) {
        float a2 = __ldg(&clsb[tid]);
#pragma unroll
        for (int kk = 0; kk < 64; kk++)
            a2 += meanv[kk] * __ldg(&clsW[kk * 10 + tid]);
        out[g * 10 + tid] = a2;
    }
}

// ---------------------------------------------------------------------------
extern "C" void kernel_launch(void* const* d_in, const int* in_sizes, int n_in,
                              void* d_out, int out_size) {
    const float* x   = (const float*)d_in[0];
    const int*   ei  = (const int*)  d_in[1];
    const int*   gid = (const int*)  d_in[2];
    const float* W1  = (const float*)d_in[3];
    const float* b1  = (const float*)d_in[4];
    const float* W2  = (const float*)d_in[5];
    const float* b2  = (const float*)d_in[6];
    const float* aW  = (const float*)d_in[7];
    const float* ab  = (const float*)d_in[8];
    const float* cW  = (const float*)d_in[9];
    const float* cb  = (const float*)d_in[10];
    float* out = (float*)d_out;
    float* hw  = out + NG * 10;

    static bool attr_done = false;
    if (!attr_done) {
        cudaFuncSetAttribute(gemm_mma_kernel<INDIM, false>,
                             cudaFuncAttributeMaxDynamicSharedMemorySize, GEMM_SMEM);
        cudaFuncSetAttribute(gemm_mma_kernel<HID, true>,
                             cudaFuncAttributeMaxDynamicSharedMemorySize, GEMM_SMEM);
        attr_done = true;
    }

    zero_kernel<<<(NN + 255) / 256, 256>>>();
    degree_kernel<<<(NE + 255) / 256, 256>>>(ei);
    norm_off_kernel<<<(NN + 255) / 256, 256>>>();
    graph_bounds_kernel<<<1, 128>>>(gid);
    scatter_kernel<<<(NE + 255) / 256, 256>>>(ei);

    // Layer 1
    gemm_mma_kernel<INDIM, false><<<(NN + 127) / 128, 256, GEMM_SMEM>>>(x, W1);
    spmm_kernel<false><<<(NN + 7) / 8, 256>>>(b1, nullptr, nullptr, nullptr);

    // Layer 2
    gemm_mma_kernel<HID, true><<<(NN + 127) / 128, 256, GEMM_SMEM>>>(nullptr, W2);
    spmm_kernel<true><<<(NN + 7) / 8, 256>>>(b2, aW, ab, hw);

    // Readout
    pool_cls_kernel<<<NG, 512>>>(cW, cb, out);
}

// round 9
// speedup vs baseline: 2.7708x; 1.0332x over previous
#include <cuda_runtime.h>
#include <cuda_bf16.h>
#include <cuda_fp16.h>
#include <cstdint>

#define NN 100000
#define NE 1600000
#define NG 64
#define HID 64
#define INDIM 128

// Scratch (__device__ globals per alloc-free rule)
__device__ __half g_buf1h[NN * 64];  // GEMM output scaled by norm_out, fp16 (SpMM source)
__device__ float4 g_buf2[NN * 16];   // activations / gated output (fp32)
__device__ float  g_norm_out[NN];
__device__ float  g_norm_in[NN];
__device__ int    g_deg_out[NN];
__device__ int    g_deg_in[NN];
__device__ int    g_fill[NN];
__device__ int    g_row_off[NN];
__device__ int    g_csr_src[NE];
__device__ int    g_total;
__device__ int    g_off[NG + 1];

// ---------------------------------------------------------------------------
__device__ __forceinline__ uint32_t smem_u32(const void* p) {
    uint32_t a;
    asm("{ .reg .u64 t; cvta.to.shared.u64 t, %1; cvt.u32.u64 %0, t; }"
        : "=r"(a) : "l"(p));
    return a;
}
__device__ __forceinline__ void ldm_x4(uint32_t* r, uint32_t addr) {
    asm volatile("ldmatrix.sync.aligned.m8n8.x4.shared.b16 {%0,%1,%2,%3}, [%4];"
                 : "=r"(r[0]), "=r"(r[1]), "=r"(r[2]), "=r"(r[3]) : "r"(addr));
}
__device__ __forceinline__ void mma_16816(float* d, const uint32_t* a,
                                          const uint32_t* b) {
    asm volatile("mma.sync.aligned.m16n8k16.row.col.f32.f16.f16.f32 "
                 "{%0,%1,%2,%3}, {%4,%5,%6,%7}, {%8,%9}, {%0,%1,%2,%3};"
                 : "+f"(d[0]), "+f"(d[1]), "+f"(d[2]), "+f"(d[3])
                 : "r"(a[0]), "r"(a[1]), "r"(a[2]), "r"(a[3]),
                   "r"(b[0]), "r"(b[1]));
}

// ---------------------------------------------------------------------------
__global__ void zero_kernel() {
    int i = blockIdx.x * blockDim.x + threadIdx.x;
    if (i < NN) { g_deg_out[i] = 0; g_deg_in[i] = 0; }
    if (i == 0) g_total = 0;
}

// Degrees + (last block) graph segment bounds via binary search on sorted gid.
// The search block runs concurrently with the degree blocks -> latency hidden.
__global__ void degree_kernel(const int* __restrict__ ei,
                              const int* __restrict__ gid) {
    if (blockIdx.x == gridDim.x - 1) {
        int t = threadIdx.x;
        if (t <= NG) {
            int lo = 0, hi = NN;          // smallest i with gid[i] >= t
            while (lo < hi) {
                int mid = (lo + hi) >> 1;
                if (__ldg(&gid[mid]) < t) lo = mid + 1; else hi = mid;
            }
            g_off[t] = lo;
        }
        return;
    }
    int e = blockIdx.x * blockDim.x + threadIdx.x;
    if (e < NE) {
        atomicAdd(&g_deg_out[ei[e]], 1);
        atomicAdd(&g_deg_in[ei[NE + e]], 1);
    }
}

// Bump-allocated CSR segments (order-free) + both norms, one pass.
__global__ void norm_off_kernel() {
    int i = blockIdx.x * blockDim.x + threadIdx.x;
    if (i < NN) {
        int deg = g_deg_in[i];
        int ro = atomicAdd(&g_total, deg);
        g_row_off[i] = ro;
        g_fill[i] = ro;
        g_norm_in[i]  = rsqrtf((float)max(deg, 1));
        g_norm_out[i] = rsqrtf((float)max(g_deg_out[i], 1));
    }
}

__global__ void scatter_kernel(const int* __restrict__ ei) {
    int e = blockIdx.x * blockDim.x + threadIdx.x;
    if (e < NE) {
        int d = ei[NE + e];
        int pos = atomicAdd(&g_fill[d], 1);
        g_csr_src[pos] = ei[e];
    }
}

// ---------------------------------------------------------------------------
// HMMA GEMM: buf1h[n][c] = fp16((X[n] @ W)[c] * norm_out[n]).
// fp32 -> fp16 hi/lo split: D = Ah*Bh + Ah*Bl + Al*Bh (fp32 accumulators).
#define APAD 72
template <int K, bool FROM_BUF2>
__global__ void __launch_bounds__(256)
gemm_mma_kernel(const float* __restrict__ Xext, const float* __restrict__ W) {
    extern __shared__ __half sm[];
    __half* Ah = sm;
    __half* Al = Ah + 128 * APAD;
    __half* Bh = Al + 128 * APAD;
    __half* Bl = Bh + 64 * APAD;
    const float* X = FROM_BUF2 ? (const float*)g_buf2 : Xext;

    int tid = threadIdx.x;
    int warp = tid >> 5, lane = tid & 31;
    int wm = warp & 3, wn = warp >> 2;
    int n0 = blockIdx.x * 128;

    float d[2][4][4];
#pragma unroll
    for (int mt = 0; mt < 2; ++mt)
#pragma unroll
        for (int nt = 0; nt < 4; ++nt)
#pragma unroll
            for (int q = 0; q < 4; ++q) d[mt][nt][q] = 0.f;

#pragma unroll
    for (int kc = 0; kc < K / 64; ++kc) {
        for (int i = tid; i < 128 * 16; i += 256) {
            int r = i >> 4, jv = i & 15;
            int n = n0 + r;
            float4 v = (n < NN)
                ? __ldg((const float4*)(X + (size_t)n * K + kc * 64) + jv)
                : make_float4(0.f, 0.f, 0.f, 0.f);
            float vv[4] = {v.x, v.y, v.z, v.w};
#pragma unroll
            for (int e = 0; e < 4; ++e) {
                __half h = __float2half_rn(vv[e]);
                __half l = __float2half_rn(vv[e] - __half2float(h));
                Ah[r * APAD + jv * 4 + e] = h;
                Al[r * APAD + jv * 4 + e] = l;
            }
        }
        for (int i = tid; i < 64 * 64; i += 256) {
            int k = i >> 6, n = i & 63;
            float w = __ldg(&W[(kc * 64 + k) * 64 + n]);
            __half h = __float2half_rn(w);
            __half l = __float2half_rn(w - __half2float(h));
            Bh[n * APAD + k] = h;
            Bl[n * APAD + k] = l;
        }
        __syncthreads();

#pragma unroll
        for (int ks = 0; ks < 4; ++ks) {
            uint32_t ah[2][4], al[2][4], bh[4][2], bl[4][2];
#pragma unroll
            for (int mt = 0; mt < 2; ++mt) {
                int row = wm * 32 + mt * 16 + (lane & 15);
                int col = ks * 16 + (lane >> 4) * 8;
                ldm_x4(ah[mt], smem_u32(&Ah[row * APAD + col]));
                ldm_x4(al[mt], smem_u32(&Al[row * APAD + col]));
            }
            int k0 = ks * 16 + (lane & 3) * 2;
#pragma unroll
            for (int nt = 0; nt < 4; ++nt) {
                int n = wn * 32 + nt * 8 + (lane >> 2);
                bh[nt][0] = *(const uint32_t*)&Bh[n * APAD + k0];
                bh[nt][1] = *(const uint32_t*)&Bh[n * APAD + k0 + 8];
                bl[nt][0] = *(const uint32_t*)&Bl[n * APAD + k0];
                bl[nt][1] = *(const uint32_t*)&Bl[n * APAD + k0 + 8];
            }
#pragma unroll
            for (int mt = 0; mt < 2; ++mt)
#pragma unroll
                for (int nt = 0; nt < 4; ++nt) {
                    mma_16816(d[mt][nt], ah[mt], bh[nt]);
                    mma_16816(d[mt][nt], ah[mt], bl[nt]);
                    mma_16816(d[mt][nt], al[mt], bh[nt]);
                }
        }
        __syncthreads();
    }

    // Epilogue: scale by norm_out, convert to fp16, write buf1h (half2 stores)
#pragma unroll
    for (int mt = 0; mt < 2; ++mt) {
        int r0 = n0 + wm * 32 + mt * 16 + (lane >> 2);
        int r1 = r0 + 8;
        float s0 = (r0 < NN) ? g_norm_out[r0] : 0.f;
        float s1 = (r1 < NN) ? g_norm_out[r1] : 0.f;
#pragma unroll
        for (int nt = 0; nt < 4; ++nt) {
            int c = wn * 32 + nt * 8 + (lane & 3) * 2;
            if (r0 < NN) {
                __half2 o = __floats2half2_rn(d[mt][nt][0] * s0, d[mt][nt][1] * s0);
                *(__half2*)&g_buf1h[(size_t)r0 * 64 + c] = o;
            }
            if (r1 < NN) {
                __half2 o = __floats2half2_rn(d[mt][nt][2] * s1, d[mt][nt][3] * s1);
                *(__half2*)&g_buf1h[(size_t)r1 * 64 + c] = o;
            }
        }
    }
}
#define GEMM_SMEM ((2 * 128 * APAD + 2 * 64 * APAD) * 2)

// ---------------------------------------------------------------------------
// CSR SpMM + fused epilogue. One warp per dst node, half2 per lane (128B rows),
// fp32 accumulation, 4-way ILP. No intra-warp degree divergence.
template <bool FINAL>
__global__ void spmm_kernel(const float* __restrict__ bias,
                            const float* __restrict__ aW,
                            const float* __restrict__ ab,
                            float* __restrict__ hw_out) {
    int n = blockIdx.x * 8 + (threadIdx.x >> 5);
    if (n >= NN) return;
    int lane = threadIdx.x & 31;
    int beg = g_row_off[n];
    int end = beg + g_deg_in[n];
    const __half2* B1 = (const __half2*)g_buf1h;   // row stride 32 half2
    float2 acc = make_float2(0.f, 0.f);
    int k = beg;
    for (; k + 4 <= end; k += 4) {
        int s0 = __ldg(&g_csr_src[k]);
        int s1 = __ldg(&g_csr_src[k + 1]);
        int s2 = __ldg(&g_csr_src[k + 2]);
        int s3 = __ldg(&g_csr_src[k + 3]);
        float2 v0 = __half22float2(B1[(size_t)s0 * 32 + lane]);
        float2 v1 = __half22float2(B1[(size_t)s1 * 32 + lane]);
        float2 v2 = __half22float2(B1[(size_t)s2 * 32 + lane]);
        float2 v3 = __half22float2(B1[(size_t)s3 * 32 + lane]);
        acc.x += (v0.x + v1.x) + (v2.x + v3.x);
        acc.y += (v0.y + v1.y) + (v2.y + v3.y);
    }
    for (; k < end; ++k) {
        int s = __ldg(&g_csr_src[k]);
        float2 v = __half22float2(B1[(size_t)s * 32 + lane]);
        acc.x += v.x; acc.y += v.y;
    }
    float ni = g_norm_in[n];
    float2 b = ((const float2*)bias)[lane];
    float2 h;
    h.x = fmaxf(acc.x * ni + b.x, 0.f);
    h.y = fmaxf(acc.y * ni + b.y, 0.f);
    float2* B2 = (float2*)g_buf2;
    if (!FINAL) {
        B2[(size_t)n * 32 + lane] = h;
    } else {
        float2 a = ((const float2*)aW)[lane];
        float p = h.x * a.x + h.y * a.y;
#pragma unroll
        for (int o = 16; o; o >>= 1) p += __shfl_xor_sync(0xffffffffu, p, o);
        float hw = 1.f / (1.f + __expf(-(p + __ldg(&ab[0]))));
        if (lane == 0) hw_out[n] = hw;
        B2[(size_t)n * 32 + lane] = make_float2(h.x * hw, h.y * hw);
    }
}

// ---------------------------------------------------------------------------
__global__ void pool_cls_kernel(const float* __restrict__ clsW,
                                const float* __restrict__ clsb,
                                float* __restrict__ out) {
    __shared__ float part[8][64];
    __shared__ float meanv[64];
    int g = blockIdx.x;
    int tid = threadIdx.x;
    int c = tid & 63, s = tid >> 6;
    int start = g_off[g], end = g_off[g + 1];
    float acc = 0.f;
    for (int n = start + s; n < end; n += 8)
        acc += ((const float*)g_buf2)[(size_t)n * 64 + c];
    part[s][c] = acc;
    __syncthreads();
    if (s == 0) {
        float tot = 0.f;
#pragma unroll
        for (int q = 0; q < 8; q++) tot += part[q][c];
        float cnt = fmaxf((float)(end - start), 1.f);
        meanv[c] = tot / cnt;
    }
    __syncthreads();
    if (tid < 10) {
        float a2 = __ldg(&clsb[tid]);
#pragma unroll
        for (int kk = 0; kk < 64; kk++)
            a2 += meanv[kk] * __ldg(&clsW[kk * 10 + tid]);
        out[g * 10 + tid] = a2;
    }
}

// ---------------------------------------------------------------------------
extern "C" void kernel_launch(void* const* d_in, const int* in_sizes, int n_in,
                              void* d_out, int out_size) {
    const float* x   = (const float*)d_in[0];
    const int*   ei  = (const int*)  d_in[1];
    const int*   gid = (const int*)  d_in[2];
    const float* W1  = (const float*)d_in[3];
    const float* b1  = (const float*)d_in[4];
    const float* W2  = (const float*)d_in[5];
    const float* b2  = (const float*)d_in[6];
    const float* aW  = (const float*)d_in[7];
    const float* ab  = (const float*)d_in[8];
    const float* cW  = (const float*)d_in[9];
    const float* cb  = (const float*)d_in[10];
    float* out = (float*)d_out;
    float* hw  = out + NG * 10;

    static bool attr_done = false;
    if (!attr_done) {
        cudaFuncSetAttribute(gemm_mma_kernel<INDIM, false>,
                             cudaFuncAttributeMaxDynamicSharedMemorySize, GEMM_SMEM);
        cudaFuncSetAttribute(gemm_mma_kernel<HID, true>,
                             cudaFuncAttributeMaxDynamicSharedMemorySize, GEMM_SMEM);
        attr_done = true;
    }

    zero_kernel<<<(NN + 255) / 256, 256>>>();
    degree_kernel<<<(NE + 255) / 256 + 1, 256>>>(ei, gid);  // +1 block: graph bounds
    norm_off_kernel<<<(NN + 255) / 256, 256>>>();
    scatter_kernel<<<(NE + 255) / 256, 256>>>(ei);

    // Layer 1
    gemm_mma_kernel<INDIM, false><<<(NN + 127) / 128, 256, GEMM_SMEM>>>(x, W1);
    spmm_kernel<false><<<(NN + 7) / 8, 256>>>(b1, nullptr, nullptr, nullptr);

    // Layer 2
    gemm_mma_kernel<HID, true><<<(NN + 127) / 128, 256, GEMM_SMEM>>>(nullptr, W2);
    spmm_kernel<true><<<(NN + 7) / 8, 256>>>(b2, aW, ab, hw);

    // Readout
    pool_cls_kernel<<<NG, 512>>>(cW, cb, out);
}